// round 7
// baseline (speedup 1.0000x reference)
#include <cuda_runtime.h>
#include <cuda_bf16.h>
#include <cstdint>

#define D_IN     256
#define H_DIM    128
#define N_SHARE  4
#define N_EXPERTS 12        // 4 shared + 2 tasks * 4 experts
#define M_TILE   64
#define KCHUNK   64
#define XS_STRIDE 260       // conflict-free A-frag LDS
#define WS_STRIDE 136       // conflict-free B-frag LDS
#define THREADS  512

// shared memory layout (floats)
#define OFF_XS    0
#define SZ_XS     (M_TILE * XS_STRIDE)          // 16640
#define OFF_WS    (OFF_XS + SZ_XS)
#define SZ_WS     (2 * KCHUNK * WS_STRIDE)      // 17408
#define OFF_WG    (OFF_WS + SZ_WS)
#define WG_TSTRIDE 2056                         // 2048 + 8 pad
#define SZ_WG     (2 * WG_TSTRIDE)              // 4112
#define OFF_GATE  (OFF_WG + SZ_WG)
#define SZ_GATE   (M_TILE * 17)                 // 1088
#define OFF_BIAS  (OFF_GATE + SZ_GATE)
#define SZ_BIAS   (N_EXPERTS * H_DIM)           // 1536
#define SMEM_FLOATS (OFF_BIAS + SZ_BIAS)        // 40784
#define SMEM_BYTES  (SMEM_FLOATS * 4)           // 163136

__device__ __forceinline__ unsigned f2tf(float x) {
    unsigned u;
    asm("cvt.rna.tf32.f32 %0, %1;" : "=r"(u) : "f"(x));
    return u;
}

__device__ __forceinline__ void mma_tf32(float* d, const unsigned* a, const unsigned* b) {
    asm volatile(
        "mma.sync.aligned.m16n8k8.row.col.f32.tf32.tf32.f32 "
        "{%0,%1,%2,%3}, {%4,%5,%6,%7}, {%8,%9}, {%0,%1,%2,%3};\n"
        : "+f"(d[0]), "+f"(d[1]), "+f"(d[2]), "+f"(d[3])
        : "r"(a[0]), "r"(a[1]), "r"(a[2]), "r"(a[3]),
          "r"(b[0]), "r"(b[1]));
}

__global__ __launch_bounds__(THREADS, 1)
void dmoe_fused_kernel(const float* __restrict__ x,
                       const float* __restrict__ Wsh,
                       const float* __restrict__ bsh,
                       const float* __restrict__ Wtk,
                       const float* __restrict__ btk,
                       const float* __restrict__ Wg,
                       const float* __restrict__ bg,
                       float* __restrict__ out,
                       int Btot)
{
    extern __shared__ float sm[];
    float* xs  = sm + OFF_XS;
    float* ws  = sm + OFF_WS;
    float* wgs = sm + OFF_WG;
    float* gs  = sm + OFF_GATE;
    float* bs  = sm + OFF_BIAS;

    const int tid  = threadIdx.x;
    const int warp = tid >> 5;
    const int lane = tid & 31;
    const int gid  = lane >> 2;          // 0..7
    const int tig  = lane & 3;           // 0..3
    const int m0   = (warp >> 2) * 16;   // 0,16,32,48 (16-row warp tile)
    const int h0   = (warp & 3) * 32;    // 0,32,64,96
    const int row0 = blockIdx.x * M_TILE;

    // issue one 64-k weight chunk (2048 float4) via cp.async into buffer `buf`
    auto issue_chunk = [&](int e, int kc, int buf) {
        const float* wsrc = (e < N_SHARE)
            ? (Wsh + (size_t)e * (D_IN * H_DIM))
            : (Wtk + (size_t)(e - N_SHARE) * (D_IN * H_DIM));
        wsrc += kc * KCHUNK * H_DIM;
        float* wdst = ws + buf * (KCHUNK * WS_STRIDE);
        #pragma unroll
        for (int j = 0; j < 4; ++j) {
            int idx = j * THREADS + tid;     // float4 index, 2048 total
            int r   = idx >> 5;              // 0..63
            int c4  = idx & 31;              // 0..31
            const float* g = wsrc + r * H_DIM + c4 * 4;
            unsigned saddr = (unsigned)__cvta_generic_to_shared(wdst + r * WS_STRIDE + c4 * 4);
            asm volatile("cp.async.ca.shared.global [%0], [%1], 16;\n"
                         :: "r"(saddr), "l"(g));
        }
        asm volatile("cp.async.commit_group;\n" ::: "memory");
    };

    // --- prologue: kick off weight chunk 0 immediately
    issue_chunk(0, 0, 0);

    // --- stage x tile (64 x 256), RNA-rounded to tf32
    {
        const float4* xg = (const float4*)(x + (size_t)row0 * D_IN);
        #pragma unroll
        for (int j = 0; j < 8; ++j) {
            int idx = j * THREADS + tid;     // 4096 float4
            int r   = idx >> 6;
            int c4  = idx & 63;
            float4 v = xg[r * 64 + c4];
            v.x = __uint_as_float(f2tf(v.x));
            v.y = __uint_as_float(f2tf(v.y));
            v.z = __uint_as_float(f2tf(v.z));
            v.w = __uint_as_float(f2tf(v.w));
            *(float4*)(xs + r * XS_STRIDE + c4 * 4) = v;
        }
    }
    // --- stage W_gate [2][256][8] (full fp32)
    {
        const float4* wgg = (const float4*)Wg;
        #pragma unroll
        for (int j = 0; j < 2; ++j) {
            int idx = j * THREADS + tid;     // 1024 float4
            int t   = idx >> 9;
            int rem = idx & 511;
            float4 v = wgg[idx];
            *(float4*)(wgs + t * WG_TSTRIDE + rem * 4) = v;
        }
    }
    // --- stage expert biases [12][128]
    for (int i = tid; i < SZ_BIAS; i += THREADS) {
        int e = i >> 7, h = i & 127;
        bs[i] = (e < N_SHARE) ? bsh[e * H_DIM + h]
                              : btk[(e - N_SHARE) * H_DIM + h];
    }
    __syncthreads();

    // --- gates: 16 warps, each handles rows 2*(warp+16*i)+half
    {
        int half = lane >> 4;
        int gi   = lane & 15;
        int t    = gi >> 3;
        int gg   = gi & 7;
        const float* wcol = wgs + t * WG_TSTRIDE + gg;
        float bias = bg[t * 8 + gg];
        #pragma unroll
        for (int i = 0; i < 2; ++i) {
            int p   = warp + 16 * i;
            int row = 2 * p + half;
            const float* xr = xs + row * XS_STRIDE;
            float acc = 0.f;
            #pragma unroll 8
            for (int k = 0; k < D_IN; ++k)
                acc = fmaf(xr[k], wcol[k * 8], acc);
            acc += bias;
            float mx = acc;
            mx = fmaxf(mx, __shfl_xor_sync(0xffffffffu, mx, 1));
            mx = fmaxf(mx, __shfl_xor_sync(0xffffffffu, mx, 2));
            mx = fmaxf(mx, __shfl_xor_sync(0xffffffffu, mx, 4));
            float ev = __expf(acc - mx);
            float s = ev;
            s += __shfl_xor_sync(0xffffffffu, s, 1);
            s += __shfl_xor_sync(0xffffffffu, s, 2);
            s += __shfl_xor_sync(0xffffffffu, s, 4);
            gs[row * 17 + gi] = ev / s;
        }
    }
    __syncthreads();

    // --- towers accumulators (registers): tw[task][nt][c]
    float tw[2][4][4];
    #pragma unroll
    for (int t = 0; t < 2; ++t)
        #pragma unroll
        for (int nt = 0; nt < 4; ++nt)
            #pragma unroll
            for (int c = 0; c < 4; ++c)
                tw[t][nt][c] = 0.f;

    // --- main loop: 12 experts x 4 k-chunks, double-buffered cp.async
    #pragma unroll 1
    for (int e = 0; e < N_EXPERTS; ++e) {
        float acc[4][4];
        #pragma unroll
        for (int nt = 0; nt < 4; ++nt)
            #pragma unroll
            for (int c = 0; c < 4; ++c)
                acc[nt][c] = 0.f;

        #pragma unroll 1
        for (int kc = 0; kc < 4; ++kc) {
            int buf    = kc & 1;
            int nchunk = e * 4 + kc + 1;
            if (nchunk < N_EXPERTS * 4) {
                issue_chunk(nchunk >> 2, nchunk & 3, (kc + 1) & 1);
                asm volatile("cp.async.wait_group 1;\n" ::: "memory");
            } else {
                asm volatile("cp.async.wait_group 0;\n" ::: "memory");
            }
            __syncthreads();

            const float* wb = ws + buf * (KCHUNK * WS_STRIDE);
            #pragma unroll
            for (int ks = 0; ks < 8; ++ks) {
                int kk = kc * KCHUNK + ks * 8;
                unsigned a[4];
                {
                    const float* xr = xs + (m0 + gid) * XS_STRIDE + kk;
                    a[0] = __float_as_uint(xr[tig]);
                    a[1] = __float_as_uint(xr[8 * XS_STRIDE + tig]);
                    a[2] = __float_as_uint(xr[tig + 4]);
                    a[3] = __float_as_uint(xr[8 * XS_STRIDE + tig + 4]);
                }
                unsigned b[4][2];
                const float* wr = wb + (ks * 8 + tig) * WS_STRIDE + h0 + gid;
                #pragma unroll
                for (int nt = 0; nt < 4; ++nt) {
                    b[nt][0] = f2tf(wr[nt * 8]);
                    b[nt][1] = f2tf(wr[nt * 8 + 4 * WS_STRIDE]);
                }
                #pragma unroll
                for (int nt = 0; nt < 4; ++nt)
                    mma_tf32(acc[nt], a, b[nt]);
            }
            __syncthreads();
        }

        // --- epilogue for expert e: bias + ReLU + gate-weighted accumulate
        {
            int rA = m0 + gid;
            int rB = rA + 8;
            if (e < N_SHARE) {
                float gA0 = gs[rA * 17 + e],     gB0 = gs[rB * 17 + e];
                float gA1 = gs[rA * 17 + 8 + e], gB1 = gs[rB * 17 + 8 + e];
                #pragma unroll
                for (int nt = 0; nt < 4; ++nt) {
                    int h = h0 + nt * 8 + tig * 2;
                    float b0 = bs[e * H_DIM + h];
                    float b1 = bs[e * H_DIM + h + 1];
                    float v0 = fmaxf(acc[nt][0] + b0, 0.f);
                    float v1 = fmaxf(acc[nt][1] + b1, 0.f);
                    float v2 = fmaxf(acc[nt][2] + b0, 0.f);
                    float v3 = fmaxf(acc[nt][3] + b1, 0.f);
                    tw[0][nt][0] += gA0 * v0;  tw[0][nt][1] += gA0 * v1;
                    tw[0][nt][2] += gB0 * v2;  tw[0][nt][3] += gB0 * v3;
                    tw[1][nt][0] += gA1 * v0;  tw[1][nt][1] += gA1 * v1;
                    tw[1][nt][2] += gB1 * v2;  tw[1][nt][3] += gB1 * v3;
                }
            } else {
                int et   = e - N_SHARE;
                int tt   = et >> 2;                    // task 0 or 1
                int gcol = tt * 8 + 4 + (et & 3);      // gate column
                float gA = gs[rA * 17 + gcol];
                float gB = gs[rB * 17 + gcol];
                float* twt = &tw[tt][0][0];
                #pragma unroll
                for (int nt = 0; nt < 4; ++nt) {
                    int h = h0 + nt * 8 + tig * 2;
                    float b0 = bs[e * H_DIM + h];
                    float b1 = bs[e * H_DIM + h + 1];
                    twt[nt * 4 + 0] += gA * fmaxf(acc[nt][0] + b0, 0.f);
                    twt[nt * 4 + 1] += gA * fmaxf(acc[nt][1] + b1, 0.f);
                    twt[nt * 4 + 2] += gB * fmaxf(acc[nt][2] + b0, 0.f);
                    twt[nt * 4 + 3] += gB * fmaxf(acc[nt][3] + b1, 0.f);
                }
            }
        }
    }

    // --- write towers [2][B][128]
    #pragma unroll
    for (int t = 0; t < 2; ++t) {
        size_t rA = (size_t)row0 + m0 + gid;
        float* baseA = out + ((size_t)t * Btot + rA) * H_DIM;
        float* baseB = baseA + 8 * H_DIM;
        #pragma unroll
        for (int nt = 0; nt < 4; ++nt) {
            int h = h0 + nt * 8 + tig * 2;
            *(float2*)(baseA + h) = make_float2(tw[t][nt][0], tw[t][nt][1]);
            *(float2*)(baseB + h) = make_float2(tw[t][nt][2], tw[t][nt][3]);
        }
    }
}

extern "C" void kernel_launch(void* const* d_in, const int* in_sizes, int n_in,
                              void* d_out, int out_size) {
    const float* x   = (const float*)d_in[0];
    const float* Wsh = (const float*)d_in[1];
    const float* bsh = (const float*)d_in[2];
    const float* Wtk = (const float*)d_in[3];
    const float* btk = (const float*)d_in[4];
    const float* Wg  = (const float*)d_in[5];
    const float* bg  = (const float*)d_in[6];
    float* out = (float*)d_out;

    int Btot = in_sizes[0] / D_IN;          // 32768
    int grid = Btot / M_TILE;               // 512

    cudaFuncSetAttribute(dmoe_fused_kernel,
                         cudaFuncAttributeMaxDynamicSharedMemorySize, SMEM_BYTES);
    dmoe_fused_kernel<<<grid, THREADS, SMEM_BYTES>>>(x, Wsh, bsh, Wtk, btk, Wg, bg, out, Btot);
}

// round 9
// speedup vs baseline: 1.2247x; 1.2247x over previous
#include <cuda_runtime.h>
#include <cstdint>

#define D_IN     256
#define H_DIM    128
#define N_SHARE  4
#define N_EXPERTS 12
#define M_TILE   64
#define KCHUNK   64
#define THREADS  256
#define EXP_WORDS 32768                 // 256*128 floats per expert image
#define CHUNK_BYTES 32768               // 64k x 128n floats

// fragment-ordered, tf32-rounded weight image [12][32768] floats
__device__ __align__(16) float g_Wfrag[N_EXPERTS * EXP_WORDS];

// ---- shared memory layout (float offsets) ----
#define OFF_AF    0
#define SZ_AF     16384                 // 32ks x 4mb x 32lane x 4 words (64KB)
#define OFF_B     16384
#define SZ_B      16384                 // 2 buffers x 8192 words (64KB)
#define OFF_WG    32768
#define WG_TSTRIDE 2056
#define SZ_WG     (2 * WG_TSTRIDE)      // 4112
#define OFF_GATE  (OFF_WG + SZ_WG)
#define SZ_GATE   (M_TILE * 17)         // 1088
#define OFF_BIAS  (OFF_GATE + SZ_GATE)
#define SZ_BIAS   (N_EXPERTS * H_DIM)   // 1536
#define SMEM_FLOATS (OFF_BIAS + SZ_BIAS)
#define SMEM_BYTES  (SMEM_FLOATS * 4)   // 158016

static __device__ __forceinline__ unsigned f2tf(float x) {
    unsigned u; asm("cvt.rna.tf32.f32 %0, %1;" : "=r"(u) : "f"(x)); return u;
}
static __device__ __forceinline__ void mma_tf32(float* d, const unsigned* a,
                                                unsigned b0, unsigned b1) {
    asm volatile(
        "mma.sync.aligned.m16n8k8.row.col.f32.tf32.tf32.f32 "
        "{%0,%1,%2,%3}, {%4,%5,%6,%7}, {%8,%9}, {%0,%1,%2,%3};\n"
        : "+f"(d[0]), "+f"(d[1]), "+f"(d[2]), "+f"(d[3])
        : "r"(a[0]), "r"(a[1]), "r"(a[2]), "r"(a[3]), "r"(b0), "r"(b1));
}

// ---------------- weight prep: transpose + tf32-round into fragment order ----
// image float4 q within expert: q = ((ks*4 + hb)*2 + g2)*32 + lane
//   lane = gid*4+tig; float4 = { W[ks*8+tig][n], W[ks*8+tig+4][n],
//                                W[ks*8+tig][n+8], W[ks*8+tig+4][n+8] }
//   with n = hb*32 + g2*16 + gid
__global__ void dmoe_wprep(const float* __restrict__ Wsh,
                           const float* __restrict__ Wtk) {
    int idx = blockIdx.x * 256 + threadIdx.x;       // float4 index
    if (idx >= N_EXPERTS * (EXP_WORDS / 4)) return;
    int e = idx >> 13;                              // /8192
    int q = idx & 8191;
    int lane = q & 31, g2 = (q >> 5) & 1, hb = (q >> 6) & 3, ks = q >> 8;
    int gid = lane >> 2, tig = lane & 3;
    int k0 = ks * 8 + tig;
    int n  = hb * 32 + g2 * 16 + gid;
    const float* W = (e < N_SHARE)
        ? (Wsh + (size_t)e * (D_IN * H_DIM))
        : (Wtk + (size_t)(e - N_SHARE) * (D_IN * H_DIM));
    float4 v;
    v.x = __uint_as_float(f2tf(W[(size_t)k0 * H_DIM + n]));
    v.y = __uint_as_float(f2tf(W[(size_t)(k0 + 4) * H_DIM + n]));
    v.z = __uint_as_float(f2tf(W[(size_t)k0 * H_DIM + n + 8]));
    v.w = __uint_as_float(f2tf(W[(size_t)(k0 + 4) * H_DIM + n + 8]));
    *(((float4*)g_Wfrag) + (size_t)e * 8192 + q) = v;
}

// ---------------- main fused kernel ----------------
__global__ __launch_bounds__(THREADS, 1)
void dmoe_fused_kernel(const float* __restrict__ x,
                       const float* __restrict__ bsh,
                       const float* __restrict__ btk,
                       const float* __restrict__ Wg,
                       const float* __restrict__ bg,
                       float* __restrict__ out,
                       int Btot)
{
    extern __shared__ float sm[];
    float* af  = sm + OFF_AF;
    float* bb  = sm + OFF_B;
    float* wgs = sm + OFF_WG;
    float* gs  = sm + OFF_GATE;
    float* bs  = sm + OFF_BIAS;

    const int tid  = threadIdx.x;
    const int warp = tid >> 5;
    const int lane = tid & 31;
    const int gid  = lane >> 2;
    const int tig  = lane & 3;
    const int m0   = (warp >> 2) * 32;       // 0 or 32
    const int mbA  = (warp >> 2) * 2;        // A m-block base (16-row blocks)
    const int hb   = warp & 3;               // 32-col h block
    const int row0 = blockIdx.x * M_TILE;

    // dense linear copy of one pre-arranged 32KB chunk into buffer `buf`
    auto issue_chunk = [&](int e, int kc, int buf) {
        const char* src = (const char*)g_Wfrag
                        + (size_t)e * (EXP_WORDS * 4) + kc * CHUNK_BYTES + tid * 16;
        unsigned dst = (unsigned)__cvta_generic_to_shared(
                        bb + buf * 8192) + tid * 16;
        #pragma unroll
        for (int j = 0; j < 8; ++j)
            asm volatile("cp.async.cg.shared.global [%0], [%1], 16;\n"
                         :: "r"(dst + j * 4096), "l"(src + j * 4096));
        asm volatile("cp.async.commit_group;\n" ::: "memory");
    };

    issue_chunk(0, 0, 0);

    // --- stage x tile into A-fragment order (tf32-rounded)
    // word(r,k) = (ks*4+mb)*128 + (r&7)*16 + (k&3)*4 + ((r>>3)&1) + 2*((k>>2)&1)
    {
        const float4* xg = (const float4*)(x + (size_t)row0 * D_IN);
        #pragma unroll
        for (int j = 0; j < 16; ++j) {
            int idx = j * THREADS + tid;     // 4096 float4
            int r = idx >> 6, q = idx & 63;
            float4 v = xg[r * 64 + q];
            float* dst = af + ((q >> 1) * 4 + (r >> 4)) * 128
                            + (r & 7) * 16 + ((r >> 3) & 1) + 2 * (q & 1);
            dst[0]  = __uint_as_float(f2tf(v.x));
            dst[4]  = __uint_as_float(f2tf(v.y));
            dst[8]  = __uint_as_float(f2tf(v.z));
            dst[12] = __uint_as_float(f2tf(v.w));
        }
    }
    // --- stage W_gate [2][256][8] raw
    {
        const float4* wgg = (const float4*)Wg;
        #pragma unroll
        for (int j = 0; j < 4; ++j) {
            int idx = j * THREADS + tid;     // 1024 float4
            int t = idx >> 9, rem = idx & 511;
            *(float4*)(wgs + t * WG_TSTRIDE + rem * 4) = wgg[idx];
        }
    }
    // --- biases
    for (int i = tid; i < SZ_BIAS; i += THREADS) {
        int e = i >> 7, h = i & 127;
        bs[i] = (e < N_SHARE) ? bsh[e * H_DIM + h]
                              : btk[(e - N_SHARE) * H_DIM + h];
    }
    __syncthreads();

    // --- gates from fragment image (broadcast reads) + softmax
    {
        int half = lane >> 4;
        int gi = lane & 15, t = gi >> 3, gg = gi & 7;
        const float* wcol = wgs + t * WG_TSTRIDE + gg;
        float bias = bg[t * 8 + gg];
        #pragma unroll
        for (int i = 0; i < 4; ++i) {
            int row = 2 * (warp + 8 * i) + half;
            const float* xb = af + (row >> 4) * 128 + (row & 7) * 16 + ((row >> 3) & 1);
            float acc = 0.f;
            #pragma unroll 4
            for (int ks = 0; ks < 32; ++ks) {
                const float* xk = xb + ks * 512;
                const float* wk = wcol + ks * 64;
                acc = fmaf(xk[0],  wk[0],  acc);
                acc = fmaf(xk[4],  wk[8],  acc);
                acc = fmaf(xk[8],  wk[16], acc);
                acc = fmaf(xk[12], wk[24], acc);
                acc = fmaf(xk[2],  wk[32], acc);
                acc = fmaf(xk[6],  wk[40], acc);
                acc = fmaf(xk[10], wk[48], acc);
                acc = fmaf(xk[14], wk[56], acc);
            }
            acc += bias;
            float mx = acc;
            mx = fmaxf(mx, __shfl_xor_sync(0xffffffffu, mx, 1));
            mx = fmaxf(mx, __shfl_xor_sync(0xffffffffu, mx, 2));
            mx = fmaxf(mx, __shfl_xor_sync(0xffffffffu, mx, 4));
            float ev = __expf(acc - mx);
            float s = ev;
            s += __shfl_xor_sync(0xffffffffu, s, 1);
            s += __shfl_xor_sync(0xffffffffu, s, 2);
            s += __shfl_xor_sync(0xffffffffu, s, 4);
            gs[row * 17 + gi] = ev / s;
        }
    }
    __syncthreads();

    float tw[2][2][4][4];
    #pragma unroll
    for (int t = 0; t < 2; ++t)
        #pragma unroll
        for (int mt = 0; mt < 2; ++mt)
            #pragma unroll
            for (int nt = 0; nt < 4; ++nt)
                #pragma unroll
                for (int c = 0; c < 4; ++c)
                    tw[t][mt][nt][c] = 0.f;

    // --- main loop
    #pragma unroll 1
    for (int e = 0; e < N_EXPERTS; ++e) {
        float acc[2][4][4];
        #pragma unroll
        for (int mt = 0; mt < 2; ++mt)
            #pragma unroll
            for (int nt = 0; nt < 4; ++nt)
                #pragma unroll
                for (int c = 0; c < 4; ++c)
                    acc[mt][nt][c] = 0.f;

        #pragma unroll 1
        for (int kc = 0; kc < 4; ++kc) {
            int buf = kc & 1;
            int nchunk = e * 4 + kc + 1;
            if (nchunk < N_EXPERTS * 4) {
                issue_chunk(nchunk >> 2, nchunk & 3, (kc + 1) & 1);
                asm volatile("cp.async.wait_group 1;\n" ::: "memory");
            } else {
                asm volatile("cp.async.wait_group 0;\n" ::: "memory");
            }
            __syncthreads();

            const float* wb = bb + buf * 8192;
            const float* apA = af + (size_t)kc * 4096 + mbA * 128 + lane * 4;
            const float* bp  = wb + hb * 256 + lane * 4;
            #pragma unroll
            for (int ks = 0; ks < 8; ++ks) {
                float4 a0 = *(const float4*)(apA + ks * 512);
                float4 a1 = *(const float4*)(apA + ks * 512 + 128);
                float4 b0 = *(const float4*)(bp + ks * 1024);
                float4 b1 = *(const float4*)(bp + ks * 1024 + 128);
                const unsigned* ua0 = (const unsigned*)&a0;
                const unsigned* ua1 = (const unsigned*)&a1;
                const unsigned* ub0 = (const unsigned*)&b0;
                const unsigned* ub1 = (const unsigned*)&b1;
                mma_tf32(acc[0][0], ua0, ub0[0], ub0[1]);
                mma_tf32(acc[0][1], ua0, ub0[2], ub0[3]);
                mma_tf32(acc[0][2], ua0, ub1[0], ub1[1]);
                mma_tf32(acc[0][3], ua0, ub1[2], ub1[3]);
                mma_tf32(acc[1][0], ua1, ub0[0], ub0[1]);
                mma_tf32(acc[1][1], ua1, ub0[2], ub0[3]);
                mma_tf32(acc[1][2], ua1, ub1[0], ub1[1]);
                mma_tf32(acc[1][3], ua1, ub1[2], ub1[3]);
            }
            __syncthreads();
        }

        // --- epilogue: bias + ReLU + gate-weighted accumulate
        #pragma unroll
        for (int mt = 0; mt < 2; ++mt) {
            int rA = m0 + mt * 16 + gid;
            int rB = rA + 8;
            if (e < N_SHARE) {
                float gA0 = gs[rA * 17 + e],     gB0 = gs[rB * 17 + e];
                float gA1 = gs[rA * 17 + 8 + e], gB1 = gs[rB * 17 + 8 + e];
                #pragma unroll
                for (int nt = 0; nt < 4; ++nt) {
                    int h = hb * 32 + nt * 8 + tig * 2;
                    float b0 = bs[e * H_DIM + h];
                    float b1 = bs[e * H_DIM + h + 1];
                    float v0 = fmaxf(acc[mt][nt][0] + b0, 0.f);
                    float v1 = fmaxf(acc[mt][nt][1] + b1, 0.f);
                    float v2 = fmaxf(acc[mt][nt][2] + b0, 0.f);
                    float v3 = fmaxf(acc[mt][nt][3] + b1, 0.f);
                    tw[0][mt][nt][0] += gA0 * v0;  tw[0][mt][nt][1] += gA0 * v1;
                    tw[0][mt][nt][2] += gB0 * v2;  tw[0][mt][nt][3] += gB0 * v3;
                    tw[1][mt][nt][0] += gA1 * v0;  tw[1][mt][nt][1] += gA1 * v1;
                    tw[1][mt][nt][2] += gB1 * v2;  tw[1][mt][nt][3] += gB1 * v3;
                }
            } else {
                int et = e - N_SHARE;
                int tt = et >> 2;
                int gcol = tt * 8 + 4 + (et & 3);
                float gA = gs[rA * 17 + gcol];
                float gB = gs[rB * 17 + gcol];
                float* twt = &tw[tt][mt][0][0];
                #pragma unroll
                for (int nt = 0; nt < 4; ++nt) {
                    int h = hb * 32 + nt * 8 + tig * 2;
                    float b0 = bs[e * H_DIM + h];
                    float b1 = bs[e * H_DIM + h + 1];
                    twt[nt * 4 + 0] += gA * fmaxf(acc[mt][nt][0] + b0, 0.f);
                    twt[nt * 4 + 1] += gA * fmaxf(acc[mt][nt][1] + b1, 0.f);
                    twt[nt * 4 + 2] += gB * fmaxf(acc[mt][nt][2] + b0, 0.f);
                    twt[nt * 4 + 3] += gB * fmaxf(acc[mt][nt][3] + b1, 0.f);
                }
            }
        }
    }

    // --- write towers [2][B][128]
    #pragma unroll
    for (int t = 0; t < 2; ++t) {
        #pragma unroll
        for (int mt = 0; mt < 2; ++mt) {
            size_t rA = (size_t)row0 + m0 + mt * 16 + gid;
            float* baseA = out + ((size_t)t * Btot + rA) * H_DIM;
            float* baseB = baseA + 8 * H_DIM;
            #pragma unroll
            for (int nt = 0; nt < 4; ++nt) {
                int h = hb * 32 + nt * 8 + tig * 2;
                *(float2*)(baseA + h) = make_float2(tw[t][mt][nt][0], tw[t][mt][nt][1]);
                *(float2*)(baseB + h) = make_float2(tw[t][mt][nt][2], tw[t][mt][nt][3]);
            }
        }
    }
}

extern "C" void kernel_launch(void* const* d_in, const int* in_sizes, int n_in,
                              void* d_out, int out_size) {
    const float* x   = (const float*)d_in[0];
    const float* Wsh = (const float*)d_in[1];
    const float* bsh = (const float*)d_in[2];
    const float* Wtk = (const float*)d_in[3];
    const float* btk = (const float*)d_in[4];
    const float* Wg  = (const float*)d_in[5];
    const float* bg  = (const float*)d_in[6];
    float* out = (float*)d_out;

    int Btot = in_sizes[0] / D_IN;          // 32768
    int nf4  = N_EXPERTS * (EXP_WORDS / 4); // 98304
    dmoe_wprep<<<(nf4 + 255) / 256, 256>>>(Wsh, Wtk);

    cudaFuncSetAttribute(dmoe_fused_kernel,
                         cudaFuncAttributeMaxDynamicSharedMemorySize, SMEM_BYTES);
    dmoe_fused_kernel<<<Btot / M_TILE, THREADS, SMEM_BYTES>>>(
        x, bsh, btk, Wg, bg, out, Btot);
}

// round 10
// speedup vs baseline: 1.2443x; 1.0160x over previous
#include <cuda_runtime.h>
#include <cstdint>

#define D_IN     256
#define H_DIM    128
#define N_SHARE  4
#define N_EXPERTS 12
#define M_TILE   64
#define THREADS  256
#define EXP_WORDS 32768                 // 256*128 floats per expert image
#define CHUNK_BYTES 16384               // 32k x 128n floats
#define NCHUNKS   (N_EXPERTS * 8)       // 96

// fragment-ordered, tf32-rounded weight image [12][32768] floats
__device__ __align__(16) float g_Wfrag[N_EXPERTS * EXP_WORDS];

// ---- shared memory layout (float offsets) ----
#define OFF_AF    0
#define SZ_AF     16384                 // 64KB: 32ks x 4mb x 128
#define OFF_B     16384
#define SZ_B      8192                  // 2 x 16KB buffers
#define OFF_GATE  24576
#define SZ_GATE   (M_TILE * 17)         // 1088
#define OFF_BIAS  (OFF_GATE + SZ_GATE)  // 25664
#define SZ_BIAS   (N_EXPERTS * H_DIM)   // 1536
#define SMEM_FLOATS (OFF_BIAS + SZ_BIAS)    // 27200
#define SMEM_BYTES  (SMEM_FLOATS * 4)       // 108800

// W_gate aliased into B buffer 1 (gates computed before buffer 1 is used)
#define OFF_WG    (OFF_B + 4096)
#define WG_TSTRIDE 2048

static __device__ __forceinline__ unsigned f2tf(float x) {
    unsigned u; asm("cvt.rna.tf32.f32 %0, %1;" : "=r"(u) : "f"(x)); return u;
}
static __device__ __forceinline__ void mma_tf32(float* d, const unsigned* a,
                                                unsigned b0, unsigned b1) {
    asm volatile(
        "mma.sync.aligned.m16n8k8.row.col.f32.tf32.tf32.f32 "
        "{%0,%1,%2,%3}, {%4,%5,%6,%7}, {%8,%9}, {%0,%1,%2,%3};\n"
        : "+f"(d[0]), "+f"(d[1]), "+f"(d[2]), "+f"(d[3])
        : "r"(a[0]), "r"(a[1]), "r"(a[2]), "r"(a[3]), "r"(b0), "r"(b1));
}

// ---------------- weight prep: transpose + tf32-round into fragment order ----
// image float4 q within expert: q = ((ks*4 + hb)*2 + g2)*32 + lane
__global__ void dmoe_wprep(const float* __restrict__ Wsh,
                           const float* __restrict__ Wtk) {
    int idx = blockIdx.x * 256 + threadIdx.x;       // float4 index
    if (idx >= N_EXPERTS * (EXP_WORDS / 4)) return;
    int e = idx >> 13;
    int q = idx & 8191;
    int lane = q & 31, g2 = (q >> 5) & 1, hb = (q >> 6) & 3, ks = q >> 8;
    int gid = lane >> 2, tig = lane & 3;
    int k0 = ks * 8 + tig;
    int n  = hb * 32 + g2 * 16 + gid;
    const float* W = (e < N_SHARE)
        ? (Wsh + (size_t)e * (D_IN * H_DIM))
        : (Wtk + (size_t)(e - N_SHARE) * (D_IN * H_DIM));
    float4 v;
    v.x = __uint_as_float(f2tf(W[(size_t)k0 * H_DIM + n]));
    v.y = __uint_as_float(f2tf(W[(size_t)(k0 + 4) * H_DIM + n]));
    v.z = __uint_as_float(f2tf(W[(size_t)k0 * H_DIM + n + 8]));
    v.w = __uint_as_float(f2tf(W[(size_t)(k0 + 4) * H_DIM + n + 8]));
    *(((float4*)g_Wfrag) + (size_t)e * 8192 + q) = v;
}

// ---------------- main fused kernel ----------------
__global__ __launch_bounds__(THREADS, 2)
void dmoe_fused_kernel(const float* __restrict__ x,
                       const float* __restrict__ bsh,
                       const float* __restrict__ btk,
                       const float* __restrict__ Wg,
                       const float* __restrict__ bg,
                       float* __restrict__ out,
                       int Btot)
{
    extern __shared__ float sm[];
    float* af  = sm + OFF_AF;
    float* bb  = sm + OFF_B;
    float* wgs = sm + OFF_WG;
    float* gs  = sm + OFF_GATE;
    float* bs  = sm + OFF_BIAS;

    const int tid  = threadIdx.x;
    const int warp = tid >> 5;
    const int lane = tid & 31;
    const int gid  = lane >> 2;
    const int tig  = lane & 3;
    const int m0   = (warp >> 2) * 32;       // 0 or 32
    const int mbA  = (warp >> 2) * 2;        // A m-block base (16-row blocks)
    const int hb   = warp & 3;               // 32-col h block
    const int row0 = blockIdx.x * M_TILE;

    // dense linear copy of one pre-arranged 16KB chunk into buffer `buf`
    auto issue_chunk = [&](int e, int kc, int buf) {
        const char* src = (const char*)g_Wfrag
                        + (size_t)e * (EXP_WORDS * 4) + kc * CHUNK_BYTES + tid * 16;
        unsigned dst = (unsigned)__cvta_generic_to_shared(
                        bb + buf * 4096) + tid * 16;
        #pragma unroll
        for (int j = 0; j < 4; ++j)
            asm volatile("cp.async.cg.shared.global [%0], [%1], 16;\n"
                         :: "r"(dst + j * 4096), "l"(src + j * 4096));
        asm volatile("cp.async.commit_group;\n" ::: "memory");
    };

    issue_chunk(0, 0, 0);    // prologue -> buffer 0 only (buffer 1 holds W_gate)

    // --- stage x tile into A-fragment order (tf32-rounded)
    {
        const float4* xg = (const float4*)(x + (size_t)row0 * D_IN);
        #pragma unroll
        for (int j = 0; j < 16; ++j) {
            int idx = j * THREADS + tid;     // 4096 float4
            int r = idx >> 6, q = idx & 63;
            float4 v = xg[r * 64 + q];
            float* dst = af + ((q >> 1) * 4 + (r >> 4)) * 128
                            + (r & 7) * 16 + ((r >> 3) & 1) + 2 * (q & 1);
            dst[0]  = __uint_as_float(f2tf(v.x));
            dst[4]  = __uint_as_float(f2tf(v.y));
            dst[8]  = __uint_as_float(f2tf(v.z));
            dst[12] = __uint_as_float(f2tf(v.w));
        }
    }
    // --- stage W_gate [2][256][8] raw into buffer-1 alias
    {
        const float4* wgg = (const float4*)Wg;
        #pragma unroll
        for (int j = 0; j < 4; ++j) {
            int idx = j * THREADS + tid;     // 1024 float4
            int t = idx >> 9, rem = idx & 511;
            *(float4*)(wgs + t * WG_TSTRIDE + rem * 4) = wgg[idx];
        }
    }
    // --- biases
    for (int i = tid; i < SZ_BIAS; i += THREADS) {
        int e = i >> 7, h = i & 127;
        bs[i] = (e < N_SHARE) ? bsh[e * H_DIM + h]
                              : btk[(e - N_SHARE) * H_DIM + h];
    }
    __syncthreads();

    // --- gates from fragment image (broadcast reads) + softmax
    {
        int half = lane >> 4;
        int gi = lane & 15, t = gi >> 3, gg = gi & 7;
        const float* wcol = wgs + t * WG_TSTRIDE + gg;
        float bias = bg[t * 8 + gg];
        #pragma unroll
        for (int i = 0; i < 4; ++i) {
            int row = 2 * (warp + 8 * i) + half;
            const float* xb = af + (row >> 4) * 128 + (row & 7) * 16 + ((row >> 3) & 1);
            float acc = 0.f;
            #pragma unroll 4
            for (int ks = 0; ks < 32; ++ks) {
                const float* xk = xb + ks * 512;
                const float* wk = wcol + ks * 64;
                acc = fmaf(xk[0],  wk[0],  acc);
                acc = fmaf(xk[4],  wk[8],  acc);
                acc = fmaf(xk[8],  wk[16], acc);
                acc = fmaf(xk[12], wk[24], acc);
                acc = fmaf(xk[2],  wk[32], acc);
                acc = fmaf(xk[6],  wk[40], acc);
                acc = fmaf(xk[10], wk[48], acc);
                acc = fmaf(xk[14], wk[56], acc);
            }
            acc += bias;
            float mx = acc;
            mx = fmaxf(mx, __shfl_xor_sync(0xffffffffu, mx, 1));
            mx = fmaxf(mx, __shfl_xor_sync(0xffffffffu, mx, 2));
            mx = fmaxf(mx, __shfl_xor_sync(0xffffffffu, mx, 4));
            float ev = __expf(acc - mx);
            float s = ev;
            s += __shfl_xor_sync(0xffffffffu, s, 1);
            s += __shfl_xor_sync(0xffffffffu, s, 2);
            s += __shfl_xor_sync(0xffffffffu, s, 4);
            gs[row * 17 + gi] = ev / s;
        }
    }
    __syncthreads();

    float tw[2][2][4][4];
    #pragma unroll
    for (int t = 0; t < 2; ++t)
        #pragma unroll
        for (int mt = 0; mt < 2; ++mt)
            #pragma unroll
            for (int nt = 0; nt < 4; ++nt)
                #pragma unroll
                for (int c = 0; c < 4; ++c)
                    tw[t][mt][nt][c] = 0.f;

    // --- main loop: 12 experts x 8 chunks (32-k), double-buffered
    #pragma unroll 1
    for (int e = 0; e < N_EXPERTS; ++e) {
        float acc[2][4][4];
        #pragma unroll
        for (int mt = 0; mt < 2; ++mt)
            #pragma unroll
            for (int nt = 0; nt < 4; ++nt)
                #pragma unroll
                for (int c = 0; c < 4; ++c)
                    acc[mt][nt][c] = 0.f;

        #pragma unroll 1
        for (int kc = 0; kc < 8; ++kc) {
            int buf = kc & 1;
            int nchunk = e * 8 + kc + 1;
            if (nchunk < NCHUNKS) {
                issue_chunk(nchunk >> 3, nchunk & 7, (kc + 1) & 1);
                asm volatile("cp.async.wait_group 1;\n" ::: "memory");
            } else {
                asm volatile("cp.async.wait_group 0;\n" ::: "memory");
            }
            __syncthreads();

            const float* wb  = bb + buf * 4096;
            const float* apA = af + kc * 2048 + mbA * 128 + lane * 4;
            const float* bp  = wb + hb * 256 + lane * 4;
            #pragma unroll
            for (int ks = 0; ks < 4; ++ks) {
                float4 a0 = *(const float4*)(apA + ks * 512);
                float4 a1 = *(const float4*)(apA + ks * 512 + 128);
                float4 b0 = *(const float4*)(bp + ks * 1024);
                float4 b1 = *(const float4*)(bp + ks * 1024 + 128);
                const unsigned* ua0 = (const unsigned*)&a0;
                const unsigned* ua1 = (const unsigned*)&a1;
                const unsigned* ub0 = (const unsigned*)&b0;
                const unsigned* ub1 = (const unsigned*)&b1;
                mma_tf32(acc[0][0], ua0, ub0[0], ub0[1]);
                mma_tf32(acc[0][1], ua0, ub0[2], ub0[3]);
                mma_tf32(acc[0][2], ua0, ub1[0], ub1[1]);
                mma_tf32(acc[0][3], ua0, ub1[2], ub1[3]);
                mma_tf32(acc[1][0], ua1, ub0[0], ub0[1]);
                mma_tf32(acc[1][1], ua1, ub0[2], ub0[3]);
                mma_tf32(acc[1][2], ua1, ub1[0], ub1[1]);
                mma_tf32(acc[1][3], ua1, ub1[2], ub1[3]);
            }
            __syncthreads();
        }

        // --- epilogue: bias + ReLU + gate-weighted accumulate
        #pragma unroll
        for (int mt = 0; mt < 2; ++mt) {
            int rA = m0 + mt * 16 + gid;
            int rB = rA + 8;
            if (e < N_SHARE) {
                float gA0 = gs[rA * 17 + e],     gB0 = gs[rB * 17 + e];
                float gA1 = gs[rA * 17 + 8 + e], gB1 = gs[rB * 17 + 8 + e];
                #pragma unroll
                for (int nt = 0; nt < 4; ++nt) {
                    int h = hb * 32 + nt * 8 + tig * 2;
                    float b0 = bs[e * H_DIM + h];
                    float b1 = bs[e * H_DIM + h + 1];
                    float v0 = fmaxf(acc[mt][nt][0] + b0, 0.f);
                    float v1 = fmaxf(acc[mt][nt][1] + b1, 0.f);
                    float v2 = fmaxf(acc[mt][nt][2] + b0, 0.f);
                    float v3 = fmaxf(acc[mt][nt][3] + b1, 0.f);
                    tw[0][mt][nt][0] += gA0 * v0;  tw[0][mt][nt][1] += gA0 * v1;
                    tw[0][mt][nt][2] += gB0 * v2;  tw[0][mt][nt][3] += gB0 * v3;
                    tw[1][mt][nt][0] += gA1 * v0;  tw[1][mt][nt][1] += gA1 * v1;
                    tw[1][mt][nt][2] += gB1 * v2;  tw[1][mt][nt][3] += gB1 * v3;
                }
            } else {
                int et = e - N_SHARE;
                int tt = et >> 2;
                int gcol = tt * 8 + 4 + (et & 3);
                float gA = gs[rA * 17 + gcol];
                float gB = gs[rB * 17 + gcol];
                float* twt = &tw[tt][mt][0][0];
                #pragma unroll
                for (int nt = 0; nt < 4; ++nt) {
                    int h = hb * 32 + nt * 8 + tig * 2;
                    float b0 = bs[e * H_DIM + h];
                    float b1 = bs[e * H_DIM + h + 1];
                    twt[nt * 4 + 0] += gA * fmaxf(acc[mt][nt][0] + b0, 0.f);
                    twt[nt * 4 + 1] += gA * fmaxf(acc[mt][nt][1] + b1, 0.f);
                    twt[nt * 4 + 2] += gB * fmaxf(acc[mt][nt][2] + b0, 0.f);
                    twt[nt * 4 + 3] += gB * fmaxf(acc[mt][nt][3] + b1, 0.f);
                }
            }
        }
    }

    // --- write towers [2][B][128]
    #pragma unroll
    for (int t = 0; t < 2; ++t) {
        #pragma unroll
        for (int mt = 0; mt < 2; ++mt) {
            size_t rA = (size_t)row0 + m0 + mt * 16 + gid;
            float* baseA = out + ((size_t)t * Btot + rA) * H_DIM;
            float* baseB = baseA + 8 * H_DIM;
            #pragma unroll
            for (int nt = 0; nt < 4; ++nt) {
                int h = hb * 32 + nt * 8 + tig * 2;
                *(float2*)(baseA + h) = make_float2(tw[t][mt][nt][0], tw[t][mt][nt][1]);
                *(float2*)(baseB + h) = make_float2(tw[t][mt][nt][2], tw[t][mt][nt][3]);
            }
        }
    }
}

extern "C" void kernel_launch(void* const* d_in, const int* in_sizes, int n_in,
                              void* d_out, int out_size) {
    const float* x   = (const float*)d_in[0];
    const float* Wsh = (const float*)d_in[1];
    const float* bsh = (const float*)d_in[2];
    const float* Wtk = (const float*)d_in[3];
    const float* btk = (const float*)d_in[4];
    const float* Wg  = (const float*)d_in[5];
    const float* bg  = (const float*)d_in[6];
    float* out = (float*)d_out;

    int Btot = in_sizes[0] / D_IN;          // 32768
    int nf4  = N_EXPERTS * (EXP_WORDS / 4); // 98304
    dmoe_wprep<<<(nf4 + 255) / 256, 256>>>(Wsh, Wtk);

    cudaFuncSetAttribute(dmoe_fused_kernel,
                         cudaFuncAttributeMaxDynamicSharedMemorySize, SMEM_BYTES);
    dmoe_fused_kernel<<<Btot / M_TILE, THREADS, SMEM_BYTES>>>(
        x, bsh, btk, Wg, bg, out, Btot);
}

// round 11
// speedup vs baseline: 1.7031x; 1.3687x over previous
#include <cuda_runtime.h>
#include <cuda_fp16.h>
#include <cstdint>

#define D_IN     256
#define H_DIM    128
#define N_SHARE  4
#define N_EXPERTS 12
#define M_TILE   64
#define THREADS  256
#define NCHUNKS  48                      // 12 experts x 4 k64-chunks
#define CHUNK_BYTES 16384                // k64 x 128n halves

// fragment-ordered fp16 weight image: [12][16ks][8ng][32lane][16B]
__device__ __align__(16) __half g_Wh[N_EXPERTS * 32768];

// ---- shared memory layout (bytes) ----
#define OFF_A    0                       // 32768: [16ks][4mb][32lane][16B]
#define OFF_B    32768                   // 4 x 16384
#define OFF_WG   (OFF_B + 3*16384)       // W_gate fp32 alias of buffer 3 (16KB)
#define OFF_GS   98304                   // gates [64][17] f32 = 4352
#define OFF_BS   102656                  // biases [12][128] f32 = 6144
#define SMEM_BYTES 108800

static __device__ __forceinline__ void mma_f16(float* d, const uint32_t* a,
                                               uint32_t b0, uint32_t b1) {
    asm volatile(
        "mma.sync.aligned.m16n8k16.row.col.f32.f16.f16.f32 "
        "{%0,%1,%2,%3}, {%4,%5,%6,%7}, {%8,%9}, {%0,%1,%2,%3};\n"
        : "+f"(d[0]), "+f"(d[1]), "+f"(d[2]), "+f"(d[3])
        : "r"(a[0]), "r"(a[1]), "r"(a[2]), "r"(a[3]), "r"(b0), "r"(b1));
}
static __device__ __forceinline__ uint32_t h2u(float lo, float hi) {
    half2 h = __floats2half2_rn(lo, hi);
    return *(uint32_t*)&h;
}

// ---------------- weight prep: fp16 fragment-ordered image ----------------
__global__ void dmoe_wprep(const float* __restrict__ Wsh,
                           const float* __restrict__ Wtk) {
    int idx = blockIdx.x * 256 + threadIdx.x;     // slot index
    if (idx >= N_EXPERTS * 4096) return;
    int e = idx >> 12;
    int s = idx & 4095;
    int lane = s & 31, ng = (s >> 5) & 7, ks = s >> 8;
    int gid = lane >> 2, tig = lane & 3;
    int k0 = ks * 16 + tig * 2;
    int na = ng * 16 + gid, nb = na + 8;
    const float* W = (e < N_SHARE)
        ? (Wsh + (size_t)e * (D_IN * H_DIM))
        : (Wtk + (size_t)(e - N_SHARE) * (D_IN * H_DIM));
    uint4 v;
    v.x = h2u(W[(size_t)k0 * H_DIM + na],       W[(size_t)(k0+1) * H_DIM + na]);
    v.y = h2u(W[(size_t)(k0+8) * H_DIM + na],   W[(size_t)(k0+9) * H_DIM + na]);
    v.z = h2u(W[(size_t)k0 * H_DIM + nb],       W[(size_t)(k0+1) * H_DIM + nb]);
    v.w = h2u(W[(size_t)(k0+8) * H_DIM + nb],   W[(size_t)(k0+9) * H_DIM + nb]);
    *(uint4*)((char*)g_Wh + (size_t)e * 65536 + (size_t)s * 16) = v;
}

// ---------------- main fused kernel ----------------
__global__ __launch_bounds__(THREADS, 2)
void dmoe_fused_kernel(const float* __restrict__ x,
                       const float* __restrict__ bsh,
                       const float* __restrict__ btk,
                       const float* __restrict__ Wg,
                       const float* __restrict__ bg,
                       float* __restrict__ out,
                       int Btot)
{
    extern __shared__ char smem[];
    float* wgs = (float*)(smem + OFF_WG);
    float* gs  = (float*)(smem + OFF_GS);
    float* bs  = (float*)(smem + OFF_BS);

    const int tid  = threadIdx.x;
    const int warp = tid >> 5;
    const int lane = tid & 31;
    const int gid  = lane >> 2;
    const int tig  = lane & 3;
    const int m0   = (warp >> 2) * 32;       // 0 or 32
    const int mbA  = (warp >> 2) * 2;        // A m-block base (16-row blocks)
    const int hb   = warp & 3;               // 32-col h block
    const int row0 = blockIdx.x * M_TILE;

    auto issue_chunk = [&](int n) {          // chunk n -> buffer n&3
        const char* src = (const char*)g_Wh
                        + (size_t)(n >> 2) * 65536 + (n & 3) * CHUNK_BYTES + tid * 16;
        unsigned dst = (unsigned)__cvta_generic_to_shared(smem + OFF_B)
                     + (n & 3) * CHUNK_BYTES + tid * 16;
        #pragma unroll
        for (int j = 0; j < 4; ++j)
            asm volatile("cp.async.cg.shared.global [%0], [%1], 16;\n"
                         :: "r"(dst + j * 4096), "l"(src + j * 4096));
        asm volatile("cp.async.commit_group;\n" ::: "memory");
    };

    // prologue: prefetch chunks 0,1,2 (buffer 3 holds W_gate until iter 0)
    issue_chunk(0); issue_chunk(1); issue_chunk(2);

    // --- stage x tile into fp16 A-fragment order
    {
        #pragma unroll
        for (int j = 0; j < 8; ++j) {
            int s = j * THREADS + tid;       // 2048 slots
            int ln = s & 31, mb = (s >> 5) & 3, ks = s >> 7;
            int g = ln >> 2, tg = ln & 3;
            int r = row0 + mb * 16 + g;
            int k0 = ks * 16 + tg * 2;
            const float* xp = x + (size_t)r * D_IN;
            float2 v00 = *(const float2*)(xp + k0);
            float2 v10 = *(const float2*)(xp + 8 * D_IN + k0);
            float2 v01 = *(const float2*)(xp + k0 + 8);
            float2 v11 = *(const float2*)(xp + 8 * D_IN + k0 + 8);
            uint4 a;
            a.x = h2u(v00.x, v00.y);
            a.y = h2u(v10.x, v10.y);
            a.z = h2u(v01.x, v01.y);
            a.w = h2u(v11.x, v11.y);
            *(uint4*)(smem + OFF_A + (size_t)s * 16) = a;
        }
    }
    // --- stage W_gate [2][256][8] fp32 into buffer-3 alias (linear copy)
    {
        const float4* wgg = (const float4*)Wg;
        #pragma unroll
        for (int j = 0; j < 4; ++j) {
            int idx = j * THREADS + tid;     // 1024 float4
            *(float4*)(wgs + idx * 4) = wgg[idx];
        }
    }
    // --- biases
    for (int i = tid; i < N_EXPERTS * H_DIM; i += THREADS) {
        int e = i >> 7, h = i & 127;
        bs[i] = (e < N_SHARE) ? bsh[e * H_DIM + h]
                              : btk[(e - N_SHARE) * H_DIM + h];
    }
    __syncthreads();

    // --- gates (x from global, W_gate from smem) + softmax
    {
        int half_ = lane >> 4;
        int gi = lane & 15, t = gi >> 3, gg = gi & 7;
        const float* wcol = wgs + t * 2048 + gg;
        float bias = bg[t * 8 + gg];
        #pragma unroll
        for (int i = 0; i < 4; ++i) {
            int row = 2 * (warp + 8 * i) + half_;
            const float* xr = x + (size_t)(row0 + row) * D_IN;
            float acc = 0.f;
            #pragma unroll 8
            for (int k = 0; k < D_IN; ++k)
                acc = fmaf(xr[k], wcol[k * 8], acc);
            acc += bias;
            float mx = acc;
            mx = fmaxf(mx, __shfl_xor_sync(0xffffffffu, mx, 1));
            mx = fmaxf(mx, __shfl_xor_sync(0xffffffffu, mx, 2));
            mx = fmaxf(mx, __shfl_xor_sync(0xffffffffu, mx, 4));
            float ev = __expf(acc - mx);
            float s = ev;
            s += __shfl_xor_sync(0xffffffffu, s, 1);
            s += __shfl_xor_sync(0xffffffffu, s, 2);
            s += __shfl_xor_sync(0xffffffffu, s, 4);
            gs[row * 17 + gi] = ev / s;
        }
    }
    __syncthreads();

    float tw[2][2][4][4];
    #pragma unroll
    for (int t = 0; t < 2; ++t)
        #pragma unroll
        for (int mt = 0; mt < 2; ++mt)
            #pragma unroll
            for (int nt = 0; nt < 4; ++nt)
                #pragma unroll
                for (int c = 0; c < 4; ++c)
                    tw[t][mt][nt][c] = 0.f;

    // --- main loop: 12 experts x 4 k64-chunks, 4-buffer / 3-deep pipeline
    #pragma unroll 1
    for (int e = 0; e < N_EXPERTS; ++e) {
        float acc[2][4][4];
        #pragma unroll
        for (int mt = 0; mt < 2; ++mt)
            #pragma unroll
            for (int nt = 0; nt < 4; ++nt)
                #pragma unroll
                for (int c = 0; c < 4; ++c)
                    acc[mt][nt][c] = 0.f;

        #pragma unroll 1
        for (int kc = 0; kc < 4; ++kc) {
            int ch = e * 4 + kc;
            if (ch <= 45)      asm volatile("cp.async.wait_group 2;\n" ::: "memory");
            else if (ch == 46) asm volatile("cp.async.wait_group 1;\n" ::: "memory");
            else               asm volatile("cp.async.wait_group 0;\n" ::: "memory");
            __syncthreads();
            if (ch + 3 < NCHUNKS) issue_chunk(ch + 3);

            const char* bufp = smem + OFF_B + (ch & 3) * CHUNK_BYTES
                             + (2 * hb) * 512 + lane * 16;
            const char* ap   = smem + OFF_A + (size_t)kc * 8192
                             + mbA * 512 + lane * 16;
            #pragma unroll
            for (int ksl = 0; ksl < 4; ++ksl) {
                uint4 A0 = *(const uint4*)(ap + ksl * 2048);
                uint4 A1 = *(const uint4*)(ap + ksl * 2048 + 512);
                uint4 B0 = *(const uint4*)(bufp + ksl * 4096);
                uint4 B1 = *(const uint4*)(bufp + ksl * 4096 + 512);
                const uint32_t* ua0 = (const uint32_t*)&A0;
                const uint32_t* ua1 = (const uint32_t*)&A1;
                mma_f16(acc[0][0], ua0, B0.x, B0.y);
                mma_f16(acc[0][1], ua0, B0.z, B0.w);
                mma_f16(acc[0][2], ua0, B1.x, B1.y);
                mma_f16(acc[0][3], ua0, B1.z, B1.w);
                mma_f16(acc[1][0], ua1, B0.x, B0.y);
                mma_f16(acc[1][1], ua1, B0.z, B0.w);
                mma_f16(acc[1][2], ua1, B1.x, B1.y);
                mma_f16(acc[1][3], ua1, B1.z, B1.w);
            }
        }

        // --- epilogue: bias + ReLU + gate-weighted accumulate
        #pragma unroll
        for (int mt = 0; mt < 2; ++mt) {
            int rA = m0 + mt * 16 + gid;
            int rB = rA + 8;
            if (e < N_SHARE) {
                float gA0 = gs[rA * 17 + e],     gB0 = gs[rB * 17 + e];
                float gA1 = gs[rA * 17 + 8 + e], gB1 = gs[rB * 17 + 8 + e];
                #pragma unroll
                for (int nt = 0; nt < 4; ++nt) {
                    int h = hb * 32 + nt * 8 + tig * 2;
                    float b0 = bs[e * H_DIM + h];
                    float b1 = bs[e * H_DIM + h + 1];
                    float v0 = fmaxf(acc[mt][nt][0] + b0, 0.f);
                    float v1 = fmaxf(acc[mt][nt][1] + b1, 0.f);
                    float v2 = fmaxf(acc[mt][nt][2] + b0, 0.f);
                    float v3 = fmaxf(acc[mt][nt][3] + b1, 0.f);
                    tw[0][mt][nt][0] += gA0 * v0;  tw[0][mt][nt][1] += gA0 * v1;
                    tw[0][mt][nt][2] += gB0 * v2;  tw[0][mt][nt][3] += gB0 * v3;
                    tw[1][mt][nt][0] += gA1 * v0;  tw[1][mt][nt][1] += gA1 * v1;
                    tw[1][mt][nt][2] += gB1 * v2;  tw[1][mt][nt][3] += gB1 * v3;
                }
            } else {
                int et = e - N_SHARE;
                int tt = et >> 2;
                int gcol = tt * 8 + 4 + (et & 3);
                float gA = gs[rA * 17 + gcol];
                float gB = gs[rB * 17 + gcol];
                float* twt = &tw[tt][mt][0][0];
                #pragma unroll
                for (int nt = 0; nt < 4; ++nt) {
                    int h = hb * 32 + nt * 8 + tig * 2;
                    float b0 = bs[e * H_DIM + h];
                    float b1 = bs[e * H_DIM + h + 1];
                    twt[nt * 4 + 0] += gA * fmaxf(acc[mt][nt][0] + b0, 0.f);
                    twt[nt * 4 + 1] += gA * fmaxf(acc[mt][nt][1] + b1, 0.f);
                    twt[nt * 4 + 2] += gB * fmaxf(acc[mt][nt][2] + b0, 0.f);
                    twt[nt * 4 + 3] += gB * fmaxf(acc[mt][nt][3] + b1, 0.f);
                }
            }
        }
    }

    // --- write towers [2][B][128]
    #pragma unroll
    for (int t = 0; t < 2; ++t) {
        #pragma unroll
        for (int mt = 0; mt < 2; ++mt) {
            size_t rA = (size_t)row0 + m0 + mt * 16 + gid;
            float* baseA = out + ((size_t)t * Btot + rA) * H_DIM;
            float* baseB = baseA + 8 * H_DIM;
            #pragma unroll
            for (int nt = 0; nt < 4; ++nt) {
                int h = hb * 32 + nt * 8 + tig * 2;
                *(float2*)(baseA + h) = make_float2(tw[t][mt][nt][0], tw[t][mt][nt][1]);
                *(float2*)(baseB + h) = make_float2(tw[t][mt][nt][2], tw[t][mt][nt][3]);
            }
        }
    }
}

extern "C" void kernel_launch(void* const* d_in, const int* in_sizes, int n_in,
                              void* d_out, int out_size) {
    const float* x   = (const float*)d_in[0];
    const float* Wsh = (const float*)d_in[1];
    const float* bsh = (const float*)d_in[2];
    const float* Wtk = (const float*)d_in[3];
    const float* btk = (const float*)d_in[4];
    const float* Wg  = (const float*)d_in[5];
    const float* bg  = (const float*)d_in[6];
    float* out = (float*)d_out;

    int Btot = in_sizes[0] / D_IN;           // 32768
    int nslots = N_EXPERTS * 4096;           // 49152
    dmoe_wprep<<<(nslots + 255) / 256, 256>>>(Wsh, Wtk);

    cudaFuncSetAttribute(dmoe_fused_kernel,
                         cudaFuncAttributeMaxDynamicSharedMemorySize, SMEM_BYTES);
    dmoe_fused_kernel<<<Btot / M_TILE, THREADS, SMEM_BYTES>>>(
        x, bsh, btk, Wg, bg, out, Btot);
}